// round 1
// baseline (speedup 1.0000x reference)
#include <cuda_runtime.h>
#include <cuda_bf16.h>
#include <cstdint>

// Problem: VectorQuantizer. x:[128,1024,64] f32, embeddings:[64,1024] f32.
// For each of N=131072 rows f: k* = argmin_k ||e_k||^2 - 2 f.e_k  (||f||^2 const),
// output row = embeddings[:, k*].
//
// Strategy: fp32-compute-bound -> use packed fma.rn.f32x2 (FFMA2, sm_103a) to
// double fp32 FMA throughput. Codebook pre-transposed to [K][D] once per launch
// (tiny prep kernel) so tiles stage into SMEM with coalesced float4s and the
// inner loop reads them as warp-uniform broadcasts (conflict-free LDS.128).

#define NUM_K 1024
#define DIM   64
#define N_ROWS (128 * 1024)
#define TILE  128
#define BLOCK 256

// Scratch (no allocations allowed): transposed codebook + per-code squared norms.
__device__ float g_embT[NUM_K * DIM];   // [k][d]
__device__ float g_norm2[NUM_K];

#define FMA_F32X2(d, a, b, c) \
    asm("fma.rn.f32x2 %0, %1, %2, %3;" : "=l"(d) : "l"(a), "l"(b), "l"(c))
#define ADD_F32X2_(d, a, b) \
    asm("add.rn.f32x2 %0, %1, %2;" : "=l"(d) : "l"(a), "l"(b))

// ---------------------------------------------------------------------------
// Prep: transpose embeddings [D][K] -> [K][D] and compute ||e_k||^2.
// 1024 threads; gmem reads coalesced along k.
// ---------------------------------------------------------------------------
__global__ void vq_prep_kernel(const float* __restrict__ emb) {
    int k = blockIdx.x * blockDim.x + threadIdx.x;
    if (k < NUM_K) {
        float acc = 0.f;
#pragma unroll
        for (int d = 0; d < DIM; d++) {
            float v = emb[d * NUM_K + k];
            g_embT[k * DIM + d] = v;
            acc = fmaf(v, v, acc);
        }
        g_norm2[k] = acc;
    }
}

// ---------------------------------------------------------------------------
// Main: one thread per row. Query packed as 32 f32x2 pairs in registers.
// Codebook walked in SMEM tiles of 128 codes; all lanes of a warp process the
// same code simultaneously -> every LDS.128 is a broadcast (no conflicts).
// ---------------------------------------------------------------------------
__global__ void __launch_bounds__(BLOCK)
vq_main_kernel(const float* __restrict__ x, float* __restrict__ out) {
    __shared__ longlong2 sm[TILE * (DIM / 4)];   // 128 codes * 64 f32 = 32 KB
    __shared__ float     snorm[TILE];

    const int row = blockIdx.x * BLOCK + threadIdx.x;

    // Load query row (64 f32) and pack into 32 x f32x2 (64-bit regs).
    const float4* xr = reinterpret_cast<const float4*>(x + (size_t)row * DIM);
    unsigned long long pf[DIM / 2];
#pragma unroll
    for (int i = 0; i < DIM / 4; i++) {
        float4 v = xr[i];
        asm("mov.b64 %0, {%1, %2};" : "=l"(pf[2 * i])     : "f"(v.x), "f"(v.y));
        asm("mov.b64 %0, {%1, %2};" : "=l"(pf[2 * i + 1]) : "f"(v.z), "f"(v.w));
    }

    float best = __int_as_float(0x7f800000);  // +inf
    int bestk = 0;

    for (int t = 0; t < NUM_K; t += TILE) {
        __syncthreads();
        // Stage tile: TILE*DIM floats = 2048 longlong2; 256 threads x 8 each,
        // fully coalesced 16B accesses, conflict-free SMEM stores.
        const longlong2* src =
            reinterpret_cast<const longlong2*>(g_embT + (size_t)t * DIM);
#pragma unroll
        for (int i = 0; i < 8; i++)
            sm[threadIdx.x + BLOCK * i] = src[threadIdx.x + BLOCK * i];
        if (threadIdx.x < TILE)
            snorm[threadIdx.x] = g_norm2[t + threadIdx.x];
        __syncthreads();

#pragma unroll 4
        for (int c = 0; c < TILE; c++) {
            const longlong2* e = sm + c * (DIM / 4);
            // Two independent accumulator chains (FFMA lat 4 / rt 2).
            unsigned long long a0 = 0ull, a1 = 0ull;  // bits of (0.f,0.f)
#pragma unroll
            for (int i = 0; i < DIM / 4; i++) {
                longlong2 ev = e[i];  // broadcast LDS.128 (warp-uniform addr)
                FMA_F32X2(a0, pf[2 * i],     ev.x, a0);
                FMA_F32X2(a1, pf[2 * i + 1], ev.y, a1);
            }
            unsigned long long as;
            ADD_F32X2_(as, a0, a1);
            float lo, hi;
            asm("mov.b64 {%0, %1}, %2;" : "=f"(lo), "=f"(hi) : "l"(as));
            float dot = lo + hi;
            float score = fmaf(-2.f, dot, snorm[c]);
            // strict < : keeps lowest index on ties (matches jnp.argmin)
            if (score < best) { best = score; bestk = t + c; }
        }
    }

    // Gather winning codebook row (L1/L2-hot, 256 KB total footprint).
    const float4* er = reinterpret_cast<const float4*>(g_embT + (size_t)bestk * DIM);
    float4* orow = reinterpret_cast<float4*>(out + (size_t)row * DIM);
#pragma unroll
    for (int i = 0; i < DIM / 4; i++)
        orow[i] = er[i];
}

extern "C" void kernel_launch(void* const* d_in, const int* in_sizes, int n_in,
                              void* d_out, int out_size) {
    const float* x   = (const float*)d_in[0];   // [128,1024,64] f32
    const float* emb = (const float*)d_in[1];   // [64,1024] f32
    float* out = (float*)d_out;

    vq_prep_kernel<<<NUM_K / 256, 256>>>(emb);
    vq_main_kernel<<<N_ROWS / BLOCK, BLOCK>>>(x, out);
}

// round 2
// speedup vs baseline: 1.2518x; 1.2518x over previous
#include <cuda_runtime.h>
#include <cuda_bf16.h>
#include <cstdint>

// VectorQuantizer: x:[128,1024,64] f32, embeddings:[64,1024] f32.
// k*(row) = argmin_k ||e_k||^2 - 2 f.e_k ; out row = embeddings[:, k*].
//
// R2: register-block 2 query rows per thread so each broadcast LDS.128 of the
// codebook feeds 4 FFMA2 (packed fp32x2 FMA). Round-1 ncu showed issue-bound
// (fma 39.6%, issue 39.3%, occ 24%); this halves LDS-per-FMA and doubles ILP,
// pushing the kernel onto the ~240us FFMA2 pipe floor. 64-thread blocks keep
// per-SM work quantization ~1.5%.

#define NUM_K 1024
#define DIM   64
#define N_ROWS (128 * 1024)
#define TILE  128
#define BLOCK 64
#define RPT   2                       // rows per thread
#define GRID  (N_ROWS / (BLOCK * RPT))  // 1024 blocks

__device__ float g_embT[NUM_K * DIM];   // codebook transposed: [k][d]
__device__ float g_norm2[NUM_K];

#define FMA_F32X2(d, a, b, c) \
    asm("fma.rn.f32x2 %0, %1, %2, %3;" : "=l"(d) : "l"(a), "l"(b), "l"(c))
#define ADD_F32X2_(d, a, b) \
    asm("add.rn.f32x2 %0, %1, %2;" : "=l"(d) : "l"(a), "l"(b))

// ---------------------------------------------------------------------------
// Prep: transpose embeddings [D][K] -> [K][D], compute ||e_k||^2.
// ---------------------------------------------------------------------------
__global__ void vq_prep_kernel(const float* __restrict__ emb) {
    int k = blockIdx.x * blockDim.x + threadIdx.x;
    if (k < NUM_K) {
        float acc = 0.f;
#pragma unroll
        for (int d = 0; d < DIM; d++) {
            float v = emb[d * NUM_K + k];
            g_embT[k * DIM + d] = v;
            acc = fmaf(v, v, acc);
        }
        g_norm2[k] = acc;
    }
}

// ---------------------------------------------------------------------------
// Main: each thread owns 2 rows. Codebook tiles staged in SMEM; all lanes
// walk the same code -> every LDS.128 is a broadcast (conflict-free), and
// each 16B load feeds 4 FFMA2 across the two queries.
// ---------------------------------------------------------------------------
__global__ void __launch_bounds__(BLOCK)
vq_main_kernel(const float* __restrict__ x, float* __restrict__ out) {
    __shared__ longlong2 sm[TILE * (DIM / 4)];   // 32 KB
    __shared__ float     snorm[TILE];

    const int r0 = blockIdx.x * (BLOCK * RPT) + threadIdx.x;
    const int r1 = r0 + BLOCK;

    // Pack both query rows as f32x2 pairs (32 x 64-bit regs each).
    unsigned long long p0[DIM / 2], p1[DIM / 2];
    {
        const float4* xr0 = reinterpret_cast<const float4*>(x + (size_t)r0 * DIM);
        const float4* xr1 = reinterpret_cast<const float4*>(x + (size_t)r1 * DIM);
#pragma unroll
        for (int i = 0; i < DIM / 4; i++) {
            float4 v = xr0[i];
            asm("mov.b64 %0, {%1, %2};" : "=l"(p0[2 * i])     : "f"(v.x), "f"(v.y));
            asm("mov.b64 %0, {%1, %2};" : "=l"(p0[2 * i + 1]) : "f"(v.z), "f"(v.w));
            float4 w = xr1[i];
            asm("mov.b64 %0, {%1, %2};" : "=l"(p1[2 * i])     : "f"(w.x), "f"(w.y));
            asm("mov.b64 %0, {%1, %2};" : "=l"(p1[2 * i + 1]) : "f"(w.z), "f"(w.w));
        }
    }

    float best0 = __int_as_float(0x7f800000), best1 = best0;
    int bk0 = 0, bk1 = 0;

    for (int t = 0; t < NUM_K; t += TILE) {
        __syncthreads();
        // Stage tile: 2048 longlong2 over 64 threads = 32 coalesced 16B each.
        const longlong2* src =
            reinterpret_cast<const longlong2*>(g_embT + (size_t)t * DIM);
#pragma unroll
        for (int i = 0; i < (TILE * DIM / 4) / BLOCK; i++)
            sm[threadIdx.x + BLOCK * i] = src[threadIdx.x + BLOCK * i];
#pragma unroll
        for (int i = 0; i < TILE / BLOCK; i++)
            snorm[threadIdx.x + BLOCK * i] = g_norm2[t + threadIdx.x + BLOCK * i];
        __syncthreads();

#pragma unroll 2
        for (int c = 0; c < TILE; c++) {
            const longlong2* e = sm + c * (DIM / 4);
            float sn = snorm[c];
            // 4 independent accumulator chains (FFMA2 lat 4 / rt 2).
            unsigned long long a0 = 0ull, a1 = 0ull, b0 = 0ull, b1 = 0ull;
#pragma unroll
            for (int i = 0; i < DIM / 4; i++) {
                longlong2 ev = e[i];  // broadcast LDS.128
                FMA_F32X2(a0, p0[2 * i],     ev.x, a0);
                FMA_F32X2(a1, p0[2 * i + 1], ev.y, a1);
                FMA_F32X2(b0, p1[2 * i],     ev.x, b0);
                FMA_F32X2(b1, p1[2 * i + 1], ev.y, b1);
            }
            unsigned long long s0, s1;
            ADD_F32X2_(s0, a0, a1);
            ADD_F32X2_(s1, b0, b1);
            float lo0, hi0, lo1, hi1;
            asm("mov.b64 {%0, %1}, %2;" : "=f"(lo0), "=f"(hi0) : "l"(s0));
            asm("mov.b64 {%0, %1}, %2;" : "=f"(lo1), "=f"(hi1) : "l"(s1));
            float sc0 = fmaf(-2.f, lo0 + hi0, sn);
            float sc1 = fmaf(-2.f, lo1 + hi1, sn);
            // strict < keeps lowest index on ties (matches jnp.argmin)
            if (sc0 < best0) { best0 = sc0; bk0 = t + c; }
            if (sc1 < best1) { best1 = sc1; bk1 = t + c; }
        }
    }

    // Gather winning codebook rows (codebook is L2-hot, 256 KB).
    const float4* e0 = reinterpret_cast<const float4*>(g_embT + (size_t)bk0 * DIM);
    const float4* e1 = reinterpret_cast<const float4*>(g_embT + (size_t)bk1 * DIM);
    float4* o0 = reinterpret_cast<float4*>(out + (size_t)r0 * DIM);
    float4* o1 = reinterpret_cast<float4*>(out + (size_t)r1 * DIM);
#pragma unroll
    for (int i = 0; i < DIM / 4; i++) { o0[i] = e0[i]; o1[i] = e1[i]; }
}

extern "C" void kernel_launch(void* const* d_in, const int* in_sizes, int n_in,
                              void* d_out, int out_size) {
    const float* x   = (const float*)d_in[0];   // [128,1024,64] f32
    const float* emb = (const float*)d_in[1];   // [64,1024] f32
    float* out = (float*)d_out;

    vq_prep_kernel<<<NUM_K / 256, 256>>>(emb);
    vq_main_kernel<<<GRID, BLOCK>>>(x, out);
}

// round 8
// speedup vs baseline: 1.7002x; 1.3582x over previous
#include <cuda_runtime.h>
#include <cuda_bf16.h>
#include <cstdint>

// VectorQuantizer: x:[128,1024,64] f32, embeddings:[64,1024] f32.
// score(f,k) = ||e_k||^2 - 2 f.e_k (||f||^2 per-row const); out = e_{argmin}.
//
// Tensor-pipe path via legacy mma.sync.m16n8k16 bf16 (tcgen05 is gated off by
// the harness's compute_103 PTX target). fp32 accuracy via 3-way bf16 split:
//   v = h + m + l;  dot = hh + hm + mh + hl + lh + mm  (abs error ~3e-7),
// all six terms accumulated into the same fp32 MMA accumulators.
//
// R7 fix: B tiles are stored code-major [n][k] (k contiguous), so the B
// fragment needs PLAIN ldmatrix.x2 (non-trans). The previous .trans variant
// (correct only for [k][n] storage) transposed every 8x8 -> rel_err 0.74.

#define NUM_K  1024
#define DIM    64
#define N_ROWS (128 * 1024)
#define MROWS  128                 // query rows per CTA
#define NT_CODES 64                // codes per B tile
#define NTILES (NUM_K / NT_CODES)  // 16
#define THREADS 128
#define GRID   (N_ROWS / MROWS)    // 1024

// device scratch (no allocations allowed)
__device__ __nv_bfloat16 g_eh[NUM_K * DIM];
__device__ __nv_bfloat16 g_em[NUM_K * DIM];
__device__ __nv_bfloat16 g_el[NUM_K * DIM];
__device__ float g_norm2[NUM_K];
__device__ float g_embT[NUM_K * DIM];    // fp32 codebook [k][d] for gather

// smem layout (bytes)
#define SM_A     0                  // 3 splits x 128 rows x 128B = 49152
#define A_SUB    16384
#define SM_B     49152              // 3 splits x 64 rows x 128B = 24576
#define B_SUB    8192
#define SM_NORM  73728              // 1024 f32
#define DYN_SMEM 77824

static __device__ __forceinline__ uint32_t smem_u32(const void* p) {
    uint32_t a;
    asm("{ .reg .u64 t; cvta.to.shared.u64 t, %1; cvt.u32.u64 %0, t; }"
        : "=r"(a) : "l"(p));
    return a;
}

#define LDSM_X4(r0, r1, r2, r3, a) \
    asm volatile("ldmatrix.sync.aligned.m8n8.x4.shared.b16 {%0,%1,%2,%3}, [%4];" \
                 : "=r"(r0), "=r"(r1), "=r"(r2), "=r"(r3) : "r"(a))
#define LDSM_X2(r0, r1, a) \
    asm volatile("ldmatrix.sync.aligned.m8n8.x2.shared.b16 {%0,%1}, [%2];" \
                 : "=r"(r0), "=r"(r1) : "r"(a))
#define MMA_BF16(c0, c1, c2, c3, a0, a1, a2, a3, b0, b1) \
    asm volatile("mma.sync.aligned.m16n8k16.row.col.f32.bf16.bf16.f32 " \
                 "{%0,%1,%2,%3}, {%4,%5,%6,%7}, {%8,%9}, {%0,%1,%2,%3};" \
                 : "+f"(c0), "+f"(c1), "+f"(c2), "+f"(c3) \
                 : "r"(a0), "r"(a1), "r"(a2), "r"(a3), "r"(b0), "r"(b1))

// ---------------------------------------------------------------------------
// Prep: 3-way bf16 split of codebook (transposed [k][d]), norms, fp32 copy.
// ---------------------------------------------------------------------------
__global__ void vq_prep_kernel(const float* __restrict__ emb) {
    int k = blockIdx.x * blockDim.x + threadIdx.x;
    if (k >= NUM_K) return;
    float acc = 0.f;
#pragma unroll
    for (int d = 0; d < DIM; d++) {
        float v = emb[d * NUM_K + k];
        acc = fmaf(v, v, acc);
        g_embT[k * DIM + d] = v;
        __nv_bfloat16 h = __float2bfloat16(v);
        float r1 = v - __bfloat162float(h);
        __nv_bfloat16 m = __float2bfloat16(r1);
        float r2 = r1 - __bfloat162float(m);
        g_eh[k * DIM + d] = h;
        g_em[k * DIM + d] = m;
        g_el[k * DIM + d] = __float2bfloat16(r2);
    }
    g_norm2[k] = acc;
}

// ---------------------------------------------------------------------------
// Main: 4 warps; warp w owns rows [32w, 32w+32) = 2 m16 tiles.
// ---------------------------------------------------------------------------
__global__ void __launch_bounds__(THREADS)
vq_main_kernel(const float* __restrict__ x, float* __restrict__ out) {
    extern __shared__ char smem[];
    const uint32_t sb = smem_u32(smem);
    const int tid = threadIdx.x;
    const int lane = tid & 31;
    const int wid = tid >> 5;

    float* snorm = reinterpret_cast<float*>(smem + SM_NORM);
#pragma unroll
    for (int i = 0; i < NUM_K / THREADS; i++)
        snorm[tid + THREADS * i] = g_norm2[tid + THREADS * i];

    // Build A: split this thread's query row into h/m/l bf16 tiles.
    // Row layout: 128B/row (64 bf16); 16B chunks XOR-swizzled by row&7 so
    // ldmatrix (8 rows x 16B per phase) is bank-conflict-free.
    {
        const float4* xr = reinterpret_cast<const float4*>(
            x + ((size_t)blockIdx.x * MROWS + tid) * DIM);
#pragma unroll
        for (int ch = 0; ch < 8; ch++) {
            float4 v0 = xr[2 * ch], v1 = xr[2 * ch + 1];
            float f[8] = {v0.x, v0.y, v0.z, v0.w, v1.x, v1.y, v1.z, v1.w};
            uint32_t hp[4], mp[4], lp[4];
#pragma unroll
            for (int j = 0; j < 4; j++) {
                __nv_bfloat16 h0 = __float2bfloat16(f[2 * j]);
                float r1 = f[2 * j] - __bfloat162float(h0);
                __nv_bfloat16 m0 = __float2bfloat16(r1);
                __nv_bfloat16 l0 = __float2bfloat16(r1 - __bfloat162float(m0));
                __nv_bfloat16 h1 = __float2bfloat16(f[2 * j + 1]);
                float s1 = f[2 * j + 1] - __bfloat162float(h1);
                __nv_bfloat16 m1 = __float2bfloat16(s1);
                __nv_bfloat16 l1 = __float2bfloat16(s1 - __bfloat162float(m1));
                __nv_bfloat162 hh(h0, h1), mm(m0, m1), ll(l0, l1);
                hp[j] = *reinterpret_cast<uint32_t*>(&hh);
                mp[j] = *reinterpret_cast<uint32_t*>(&mm);
                lp[j] = *reinterpret_cast<uint32_t*>(&ll);
            }
            uint32_t off = tid * 128 + ((ch ^ (tid & 7)) << 4);
            *reinterpret_cast<uint4*>(smem + SM_A + off) =
                make_uint4(hp[0], hp[1], hp[2], hp[3]);
            *reinterpret_cast<uint4*>(smem + SM_A + A_SUB + off) =
                make_uint4(mp[0], mp[1], mp[2], mp[3]);
            *reinterpret_cast<uint4*>(smem + SM_A + 2 * A_SUB + off) =
                make_uint4(lp[0], lp[1], lp[2], lp[3]);
        }
    }

    // per-lane running argmin: slot = mt*2 + half (half: rows +0 / +8)
    float best[4];
    int bidx[4];
#pragma unroll
    for (int s = 0; s < 4; s++) { best[s] = __int_as_float(0x7f800000); bidx[s] = 0; }

    const int SA[6] = {0, 0, 1, 0, 2, 1};   // (h,h)(h,m)(m,h)(h,l)(l,h)(m,m)
    const int SB[6] = {0, 1, 0, 2, 0, 1};

    for (int nt = 0; nt < NTILES; nt++) {
        __syncthreads();  // prior tile's ldmatrix reads done; A ready on nt=0
        // Stage B tile: 64 codes x 64 dims x 3 splits, swizzled like A.
        {
            const int base = nt * NT_CODES * DIM;
#pragma unroll
            for (int s = 0; s < 3; s++) {
                const __nv_bfloat16* g = (s == 0) ? g_eh : (s == 1) ? g_em : g_el;
                const uint4* src = reinterpret_cast<const uint4*>(g + base);
#pragma unroll
                for (int i = 0; i < 4; i++) {
                    int q = tid + THREADS * i;          // 16B chunk 0..511
                    int row = q >> 3, ch = q & 7;
                    *reinterpret_cast<uint4*>(
                        smem + SM_B + s * B_SUB + row * 128 +
                        ((ch ^ (row & 7)) << 4)) = src[q];
                }
            }
        }
        __syncthreads();

        float cc[2][8][4];
#pragma unroll
        for (int mt = 0; mt < 2; mt++)
#pragma unroll
            for (int n8 = 0; n8 < 8; n8++)
#pragma unroll
                for (int j = 0; j < 4; j++) cc[mt][n8][j] = 0.f;

#pragma unroll
        for (int term = 0; term < 6; term++) {
            const uint32_t aBase = sb + SM_A + SA[term] * A_SUB;
            const uint32_t bBase = sb + SM_B + SB[term] * B_SUB;
#pragma unroll
            for (int ks = 0; ks < 4; ks++) {
                uint32_t a[2][4];
#pragma unroll
                for (int mt = 0; mt < 2; mt++) {
                    int r = wid * 32 + mt * 16 + (lane & 15);
                    uint32_t ad = aBase + r * 128 +
                        (((2 * ks + (lane >> 4)) ^ (lane & 7)) << 4);
                    LDSM_X4(a[mt][0], a[mt][1], a[mt][2], a[mt][3], ad);
                }
#pragma unroll
                for (int n8 = 0; n8 < 8; n8++) {
                    // B stored [n][k] (k contiguous) -> NON-trans ldmatrix
                    // yields lane l: (n = l/4, k = 2*(l%4)+h), regs k0-7/k8-15.
                    int n = n8 * 8 + (lane & 7);
                    uint32_t bd = bBase + n * 128 +
                        (((2 * ks + ((lane >> 3) & 1)) ^ (lane & 7)) << 4);
                    uint32_t b0, b1;
                    LDSM_X2(b0, b1, bd);
#pragma unroll
                    for (int mt = 0; mt < 2; mt++)
                        MMA_BF16(cc[mt][n8][0], cc[mt][n8][1],
                                 cc[mt][n8][2], cc[mt][n8][3],
                                 a[mt][0], a[mt][1], a[mt][2], a[mt][3], b0, b1);
                }
            }
        }

        // Fused epilogue: score = norm2 - 2*dot, running argmin per row-slot.
#pragma unroll
        for (int n8 = 0; n8 < 8; n8++) {
            int col = nt * NT_CODES + n8 * 8 + (lane & 3) * 2;
            float sn0 = snorm[col], sn1 = snorm[col + 1];
#pragma unroll
            for (int mt = 0; mt < 2; mt++) {
                float s00 = fmaf(-2.f, cc[mt][n8][0], sn0);
                float s01 = fmaf(-2.f, cc[mt][n8][1], sn1);
                float s10 = fmaf(-2.f, cc[mt][n8][2], sn0);
                float s11 = fmaf(-2.f, cc[mt][n8][3], sn1);
                int s = mt * 2;
                if (s00 < best[s]) { best[s] = s00; bidx[s] = col; }
                if (s01 < best[s]) { best[s] = s01; bidx[s] = col + 1; }
                if (s10 < best[s + 1]) { best[s + 1] = s10; bidx[s + 1] = col; }
                if (s11 < best[s + 1]) { best[s + 1] = s11; bidx[s + 1] = col + 1; }
            }
        }
    }

    // Cross-lane reduce within each quad (lanes sharing a row), idx tiebreak.
#pragma unroll
    for (int s = 0; s < 4; s++) {
#pragma unroll
        for (int off = 1; off <= 2; off <<= 1) {
            float ob = __shfl_xor_sync(0xffffffffu, best[s], off);
            int oi = __shfl_xor_sync(0xffffffffu, bidx[s], off);
            if (ob < best[s] || (ob == best[s] && oi < bidx[s])) {
                best[s] = ob;
                bidx[s] = oi;
            }
        }
    }

    __syncthreads();
    int* sidx = reinterpret_cast<int*>(smem + SM_B);   // B buffer now free
    if ((lane & 3) == 0) {
#pragma unroll
        for (int s = 0; s < 4; s++) {
            int row = wid * 32 + (s >> 1) * 16 + (lane >> 2) + (s & 1) * 8;
            sidx[row] = bidx[s];
        }
    }
    __syncthreads();

    // Gather winning fp32 codebook row; thread tid handles query row tid.
    {
        int k = sidx[tid];
        const float4* e = reinterpret_cast<const float4*>(g_embT + (size_t)k * DIM);
        float4* o = reinterpret_cast<float4*>(
            out + ((size_t)blockIdx.x * MROWS + tid) * DIM);
#pragma unroll
        for (int i = 0; i < DIM / 4; i++) o[i] = e[i];
    }
}

extern "C" void kernel_launch(void* const* d_in, const int* in_sizes, int n_in,
                              void* d_out, int out_size) {
    const float* x   = (const float*)d_in[0];   // [128,1024,64] f32
    const float* emb = (const float*)d_in[1];   // [64,1024] f32
    float* out = (float*)d_out;

    // Idempotent, called every launch (no static guards per harness rules).
    cudaFuncSetAttribute(vq_main_kernel,
                         cudaFuncAttributeMaxDynamicSharedMemorySize, DYN_SMEM);

    vq_prep_kernel<<<NUM_K / 256, 256>>>(emb);
    vq_main_kernel<<<GRID, THREADS, DYN_SMEM>>>(x, out);
}

// round 9
// speedup vs baseline: 2.1909x; 1.2886x over previous
#include <cuda_runtime.h>
#include <cuda_bf16.h>
#include <cstdint>

// VectorQuantizer: x:[128,1024,64] f32, embeddings:[64,1024] f32.
// score(f,k) = ||e_k||^2 - 2 f.e_k (||f||^2 per-row const); out = e_{argmin}.
//
// Tensor path: legacy mma.sync.m16n8k16 bf16 (tcgen05 gated off by the
// harness's compute_103 PTX target). fp32 accuracy via 3-way bf16 split:
//   v = h + m + l;  dot = hh + hm + mh + hl + lh + mm  (abs err ~3e-7).
//
// R9: close the 45% tensor-idle gap seen in R8 ncu (tensor=55.6%):
//  - cp.async double-buffered B staging (prefetch nt+1 during MMA of nt)
//  - A fragments hoisted per-ks (reused across all 6 split terms)
//  - B fragments via ldmatrix.x4 (two n8 blocks per instruction)

#define NUM_K  1024
#define DIM    64
#define N_ROWS (128 * 1024)
#define MROWS  128
#define NT_CODES 64
#define NTILES (NUM_K / NT_CODES)  // 16
#define THREADS 128
#define GRID   (N_ROWS / MROWS)    // 1024

__device__ __nv_bfloat16 g_eh[NUM_K * DIM];
__device__ __nv_bfloat16 g_em[NUM_K * DIM];
__device__ __nv_bfloat16 g_el[NUM_K * DIM];
__device__ float g_norm2[NUM_K];
__device__ float g_embT[NUM_K * DIM];    // fp32 codebook [k][d] for gather

// smem layout (bytes)
#define SM_A     0                  // 3 splits x 128 rows x 128B
#define A_SUB    16384
#define SM_B     49152              // 2 buffers x 3 splits x 64 rows x 128B
#define BUFB     24576
#define B_SUB    8192
#define SM_NORM  98304              // 1024 f32
#define DYN_SMEM 102400

static __device__ __forceinline__ uint32_t smem_u32(const void* p) {
    uint32_t a;
    asm("{ .reg .u64 t; cvta.to.shared.u64 t, %1; cvt.u32.u64 %0, t; }"
        : "=r"(a) : "l"(p));
    return a;
}
static __device__ __forceinline__ void cp_async16(uint32_t dst, const void* src) {
    asm volatile("cp.async.cg.shared.global [%0], [%1], 16;"
                 :: "r"(dst), "l"(src));
}

#define LDSM_X4(r0, r1, r2, r3, a) \
    asm volatile("ldmatrix.sync.aligned.m8n8.x4.shared.b16 {%0,%1,%2,%3}, [%4];" \
                 : "=r"(r0), "=r"(r1), "=r"(r2), "=r"(r3) : "r"(a))
#define MMA_BF16(c0, c1, c2, c3, a0, a1, a2, a3, b0, b1) \
    asm volatile("mma.sync.aligned.m16n8k16.row.col.f32.bf16.bf16.f32 " \
                 "{%0,%1,%2,%3}, {%4,%5,%6,%7}, {%8,%9}, {%0,%1,%2,%3};" \
                 : "+f"(c0), "+f"(c1), "+f"(c2), "+f"(c3) \
                 : "r"(a0), "r"(a1), "r"(a2), "r"(a3), "r"(b0), "r"(b1))

// ---------------------------------------------------------------------------
__global__ void vq_prep_kernel(const float* __restrict__ emb) {
    int k = blockIdx.x * blockDim.x + threadIdx.x;
    if (k >= NUM_K) return;
    float acc = 0.f;
#pragma unroll
    for (int d = 0; d < DIM; d++) {
        float v = emb[d * NUM_K + k];
        acc = fmaf(v, v, acc);
        g_embT[k * DIM + d] = v;
        __nv_bfloat16 h = __float2bfloat16(v);
        float r1 = v - __bfloat162float(h);
        __nv_bfloat16 m = __float2bfloat16(r1);
        float r2 = r1 - __bfloat162float(m);
        g_eh[k * DIM + d] = h;
        g_em[k * DIM + d] = m;
        g_el[k * DIM + d] = __float2bfloat16(r2);
    }
    g_norm2[k] = acc;
}

// ---------------------------------------------------------------------------
__global__ void __launch_bounds__(THREADS)
vq_main_kernel(const float* __restrict__ x, float* __restrict__ out) {
    extern __shared__ char smem[];
    const uint32_t sb = smem_u32(smem);
    const int tid = threadIdx.x;
    const int lane = tid & 31;
    const int wid = tid >> 5;

    // Stage B tile nt into buffer buf via cp.async (16B granules, swizzled).
    auto stageB = [&](int nt, int buf) {
        const int base = nt * NT_CODES * DIM;
#pragma unroll
        for (int s = 0; s < 3; s++) {
            const __nv_bfloat16* g = (s == 0) ? g_eh : (s == 1) ? g_em : g_el;
#pragma unroll
            for (int i = 0; i < 4; i++) {
                int q = tid + THREADS * i;          // 16B chunk 0..511
                int row = q >> 3, ch = q & 7;
                uint32_t dst = sb + SM_B + buf * BUFB + s * B_SUB +
                               row * 128 + ((ch ^ (row & 7)) << 4);
                cp_async16(dst, reinterpret_cast<const char*>(g + base) + q * 16);
            }
        }
    };

    // Kick prefetch of tile 0 immediately.
    stageB(0, 0);
    asm volatile("cp.async.commit_group;");

    float* snorm = reinterpret_cast<float*>(smem + SM_NORM);
#pragma unroll
    for (int i = 0; i < NUM_K / THREADS; i++)
        snorm[tid + THREADS * i] = g_norm2[tid + THREADS * i];

    // Build A: split this thread's query row into h/m/l bf16 tiles.
    // 128B/row; 16B chunks XOR-swizzled by row&7 (conflict-free ldmatrix).
    {
        const float4* xr = reinterpret_cast<const float4*>(
            x + ((size_t)blockIdx.x * MROWS + tid) * DIM);
#pragma unroll
        for (int ch = 0; ch < 8; ch++) {
            float4 v0 = xr[2 * ch], v1 = xr[2 * ch + 1];
            float f[8] = {v0.x, v0.y, v0.z, v0.w, v1.x, v1.y, v1.z, v1.w};
            uint32_t hp[4], mp[4], lp[4];
#pragma unroll
            for (int j = 0; j < 4; j++) {
                __nv_bfloat16 h0 = __float2bfloat16(f[2 * j]);
                float r1 = f[2 * j] - __bfloat162float(h0);
                __nv_bfloat16 m0 = __float2bfloat16(r1);
                __nv_bfloat16 l0 = __float2bfloat16(r1 - __bfloat162float(m0));
                __nv_bfloat16 h1 = __float2bfloat16(f[2 * j + 1]);
                float s1 = f[2 * j + 1] - __bfloat162float(h1);
                __nv_bfloat16 m1 = __float2bfloat16(s1);
                __nv_bfloat16 l1 = __float2bfloat16(s1 - __bfloat162float(m1));
                __nv_bfloat162 hh(h0, h1), mm(m0, m1), ll(l0, l1);
                hp[j] = *reinterpret_cast<uint32_t*>(&hh);
                mp[j] = *reinterpret_cast<uint32_t*>(&mm);
                lp[j] = *reinterpret_cast<uint32_t*>(&ll);
            }
            uint32_t off = tid * 128 + ((ch ^ (tid & 7)) << 4);
            *reinterpret_cast<uint4*>(smem + SM_A + off) =
                make_uint4(hp[0], hp[1], hp[2], hp[3]);
            *reinterpret_cast<uint4*>(smem + SM_A + A_SUB + off) =
                make_uint4(mp[0], mp[1], mp[2], mp[3]);
            *reinterpret_cast<uint4*>(smem + SM_A + 2 * A_SUB + off) =
                make_uint4(lp[0], lp[1], lp[2], lp[3]);
        }
    }

    float best[4];
    int bidx[4];
#pragma unroll
    for (int s = 0; s < 4; s++) { best[s] = __int_as_float(0x7f800000); bidx[s] = 0; }

    const int SA[6] = {0, 0, 1, 0, 2, 1};   // (h,h)(h,m)(m,h)(h,l)(l,h)(m,m)
    const int SB[6] = {0, 1, 0, 2, 0, 1};

    for (int nt = 0; nt < NTILES; nt++) {
        const int cur = nt & 1;
        // Prefetch next tile into the other buffer, then wait for current.
        if (nt + 1 < NTILES) {
            stageB(nt + 1, cur ^ 1);
            asm volatile("cp.async.commit_group;");
            asm volatile("cp.async.wait_group 1;");
        } else {
            asm volatile("cp.async.wait_group 0;");
        }
        __syncthreads();   // current buffer (and A/norms on nt=0) visible

        float cc[2][8][4];
#pragma unroll
        for (int mt = 0; mt < 2; mt++)
#pragma unroll
            for (int n8 = 0; n8 < 8; n8++)
#pragma unroll
                for (int j = 0; j < 4; j++) cc[mt][n8][j] = 0.f;

#pragma unroll
        for (int ks = 0; ks < 4; ks++) {
            // Hoist A fragments: all 3 splits for both m-tiles at this ks.
            uint32_t a[3][2][4];
#pragma unroll
            for (int sp = 0; sp < 3; sp++)
#pragma unroll
                for (int mt = 0; mt < 2; mt++) {
                    int r = wid * 32 + mt * 16 + (lane & 15);
                    uint32_t ad = sb + SM_A + sp * A_SUB + r * 128 +
                        (((2 * ks + (lane >> 4)) ^ (lane & 7)) << 4);
                    LDSM_X4(a[sp][mt][0], a[sp][mt][1], a[sp][mt][2],
                            a[sp][mt][3], ad);
                }
#pragma unroll
            for (int term = 0; term < 6; term++) {
                const uint32_t bBase = sb + SM_B + cur * BUFB + SB[term] * B_SUB;
#pragma unroll
                for (int np = 0; np < 4; np++) {
                    // x4 B load: two n8 blocks (rows 16np+0..7 / +8..15),
                    // chunks 2ks / 2ks+1. n&7 == lane&7 for swizzle.
                    int n = 16 * np + ((lane >> 4) << 3) + (lane & 7);
                    int ch = 2 * ks + ((lane >> 3) & 1);
                    uint32_t bd = bBase + n * 128 + ((ch ^ (lane & 7)) << 4);
                    uint32_t b0, b1, b2, b3;
                    LDSM_X4(b0, b1, b2, b3, bd);
#pragma unroll
                    for (int mt = 0; mt < 2; mt++) {
                        MMA_BF16(cc[mt][2 * np][0], cc[mt][2 * np][1],
                                 cc[mt][2 * np][2], cc[mt][2 * np][3],
                                 a[SA[term]][mt][0], a[SA[term]][mt][1],
                                 a[SA[term]][mt][2], a[SA[term]][mt][3], b0, b1);
                        MMA_BF16(cc[mt][2 * np + 1][0], cc[mt][2 * np + 1][1],
                                 cc[mt][2 * np + 1][2], cc[mt][2 * np + 1][3],
                                 a[SA[term]][mt][0], a[SA[term]][mt][1],
                                 a[SA[term]][mt][2], a[SA[term]][mt][3], b2, b3);
                    }
                }
            }
        }

        // Fused epilogue: score = norm2 - 2*dot, running argmin per row-slot.
#pragma unroll
        for (int n8 = 0; n8 < 8; n8++) {
            int col = nt * NT_CODES + n8 * 8 + (lane & 3) * 2;
            float sn0 = snorm[col], sn1 = snorm[col + 1];
#pragma unroll
            for (int mt = 0; mt < 2; mt++) {
                float s00 = fmaf(-2.f, cc[mt][n8][0], sn0);
                float s01 = fmaf(-2.f, cc[mt][n8][1], sn1);
                float s10 = fmaf(-2.f, cc[mt][n8][2], sn0);
                float s11 = fmaf(-2.f, cc[mt][n8][3], sn1);
                int s = mt * 2;
                if (s00 < best[s]) { best[s] = s00; bidx[s] = col; }
                if (s01 < best[s]) { best[s] = s01; bidx[s] = col + 1; }
                if (s10 < best[s + 1]) { best[s + 1] = s10; bidx[s + 1] = col; }
                if (s11 < best[s + 1]) { best[s + 1] = s11; bidx[s + 1] = col + 1; }
            }
        }
        __syncthreads();   // all reads of buffer `cur` done before overwrite
    }

    // Cross-lane reduce within each quad (lanes sharing a row), idx tiebreak.
#pragma unroll
    for (int s = 0; s < 4; s++) {
#pragma unroll
        for (int off = 1; off <= 2; off <<= 1) {
            float ob = __shfl_xor_sync(0xffffffffu, best[s], off);
            int oi = __shfl_xor_sync(0xffffffffu, bidx[s], off);
            if (ob < best[s] || (ob == best[s] && oi < bidx[s])) {
                best[s] = ob;
                bidx[s] = oi;
            }
        }
    }

    __syncthreads();
    int* sidx = reinterpret_cast<int*>(smem + SM_B);   // B buffers now free
    if ((lane & 3) == 0) {
#pragma unroll
        for (int s = 0; s < 4; s++) {
            int row = wid * 32 + (s >> 1) * 16 + (lane >> 2) + (s & 1) * 8;
            sidx[row] = bidx[s];
        }
    }
    __syncthreads();

    // Gather winning fp32 codebook row; thread tid handles query row tid.
    {
        int k = sidx[tid];
        const float4* e = reinterpret_cast<const float4*>(g_embT + (size_t)k * DIM);
        float4* o = reinterpret_cast<float4*>(
            out + ((size_t)blockIdx.x * MROWS + tid) * DIM);
#pragma unroll
        for (int i = 0; i < DIM / 4; i++) o[i] = e[i];
    }
}

extern "C" void kernel_launch(void* const* d_in, const int* in_sizes, int n_in,
                              void* d_out, int out_size) {
    const float* x   = (const float*)d_in[0];   // [128,1024,64] f32
    const float* emb = (const float*)d_in[1];   // [64,1024] f32
    float* out = (float*)d_out;

    cudaFuncSetAttribute(vq_main_kernel,
                         cudaFuncAttributeMaxDynamicSharedMemorySize, DYN_SMEM);

    vq_prep_kernel<<<NUM_K / 256, 256>>>(emb);
    vq_main_kernel<<<GRID, THREADS, DYN_SMEM>>>(x, out);
}

// round 10
// speedup vs baseline: 2.4775x; 1.1308x over previous
#include <cuda_runtime.h>
#include <cuda_fp16.h>
#include <cstdint>

// VectorQuantizer: x:[128,1024,64] f32, embeddings:[64,1024] f32.
// score(f,k) = ||e_k||^2 - 2 f.e_k (||f||^2 per-row const); out = e_{argmin}.
//
// Tensor path: legacy mma.sync.m16n8k16 (tcgen05 gated off by the harness's
// compute_103 PTX target).
//
// R10: fp16 2-way split, FOUR terms (vs bf16 3-way / six terms in R9):
//   v = h + m + l,  h=fp16(v), m=fp16(v-h), |l| <= 2^-22 |v|
//   dot((h+m)_f, (h+m)_e) = hh + hm + mh + mm   -- computed exactly;
// only the representation residual l is dropped -> distance noise ~2e-6,
// same class as the scalar-fp32 kernel that passed with zero argmin flips.
// MMA work drops 33% (HMMA floor ~170us -> ~113us). SMEM 100K->68K allows
// 3 CTAs/SM for better overlap.

#define NUM_K  1024
#define DIM    64
#define N_ROWS (128 * 1024)
#define MROWS  128
#define NT_CODES 64
#define NTILES (NUM_K / NT_CODES)  // 16
#define THREADS 128
#define GRID   (N_ROWS / MROWS)    // 1024

__device__ __half g_eh[NUM_K * DIM];
__device__ __half g_em[NUM_K * DIM];
__device__ float g_norm2[NUM_K];
__device__ float g_embT[NUM_K * DIM];    // fp32 codebook [k][d] for gather

// smem layout (bytes)
#define SM_A     0                  // 2 splits x 128 rows x 128B = 32768
#define A_SUB    16384
#define SM_B     32768              // 2 buffers x 2 splits x 64 rows x 128B
#define BUFB     16384
#define B_SUB    8192
#define SM_NORM  65536              // 1024 f32
#define DYN_SMEM 69632

static __device__ __forceinline__ uint32_t smem_u32(const void* p) {
    uint32_t a;
    asm("{ .reg .u64 t; cvta.to.shared.u64 t, %1; cvt.u32.u64 %0, t; }"
        : "=r"(a) : "l"(p));
    return a;
}
static __device__ __forceinline__ void cp_async16(uint32_t dst, const void* src) {
    asm volatile("cp.async.cg.shared.global [%0], [%1], 16;"
                 :: "r"(dst), "l"(src));
}

#define LDSM_X4(r0, r1, r2, r3, a) \
    asm volatile("ldmatrix.sync.aligned.m8n8.x4.shared.b16 {%0,%1,%2,%3}, [%4];" \
                 : "=r"(r0), "=r"(r1), "=r"(r2), "=r"(r3) : "r"(a))
#define MMA_F16(c0, c1, c2, c3, a0, a1, a2, a3, b0, b1) \
    asm volatile("mma.sync.aligned.m16n8k16.row.col.f32.f16.f16.f32 " \
                 "{%0,%1,%2,%3}, {%4,%5,%6,%7}, {%8,%9}, {%0,%1,%2,%3};" \
                 : "+f"(c0), "+f"(c1), "+f"(c2), "+f"(c3) \
                 : "r"(a0), "r"(a1), "r"(a2), "r"(a3), "r"(b0), "r"(b1))

// ---------------------------------------------------------------------------
// Prep 1: elementwise transpose + fp16 split. i = d*1024 + k (coalesced read).
// ---------------------------------------------------------------------------
__global__ void vq_split_kernel(const float* __restrict__ emb) {
    int i = blockIdx.x * blockDim.x + threadIdx.x;   // 65536 elements
    int d = i >> 10, k = i & 1023;
    float v = emb[i];
    __half h = __float2half_rn(v);
    __half m = __float2half_rn(v - __half2float(h));
    g_embT[k * DIM + d] = v;
    g_eh[k * DIM + d] = h;
    g_em[k * DIM + d] = m;
}
// Prep 2: per-code squared norms (reads transposed rows contiguously).
__global__ void vq_norm_kernel() {
    int k = blockIdx.x * blockDim.x + threadIdx.x;
    const float4* r = reinterpret_cast<const float4*>(g_embT + (size_t)k * DIM);
    float acc = 0.f;
#pragma unroll
    for (int i = 0; i < DIM / 4; i++) {
        float4 v = r[i];
        acc = fmaf(v.x, v.x, acc);
        acc = fmaf(v.y, v.y, acc);
        acc = fmaf(v.z, v.z, acc);
        acc = fmaf(v.w, v.w, acc);
    }
    g_norm2[k] = acc;
}

// ---------------------------------------------------------------------------
__global__ void __launch_bounds__(THREADS, 3)
vq_main_kernel(const float* __restrict__ x, float* __restrict__ out) {
    extern __shared__ char smem[];
    const uint32_t sb = smem_u32(smem);
    const int tid = threadIdx.x;
    const int lane = tid & 31;
    const int wid = tid >> 5;

    // Stage B tile nt into buffer buf via cp.async (16B granules, swizzled).
    auto stageB = [&](int nt, int buf) {
        const int base = nt * NT_CODES * DIM;
#pragma unroll
        for (int s = 0; s < 2; s++) {
            const __half* g = (s == 0) ? g_eh : g_em;
#pragma unroll
            for (int i = 0; i < 4; i++) {
                int q = tid + THREADS * i;          // 16B chunk 0..511
                int row = q >> 3, ch = q & 7;
                uint32_t dst = sb + SM_B + buf * BUFB + s * B_SUB +
                               row * 128 + ((ch ^ (row & 7)) << 4);
                cp_async16(dst, reinterpret_cast<const char*>(g + base) + q * 16);
            }
        }
    };

    stageB(0, 0);
    asm volatile("cp.async.commit_group;");

    float* snorm = reinterpret_cast<float*>(smem + SM_NORM);
#pragma unroll
    for (int i = 0; i < NUM_K / THREADS; i++)
        snorm[tid + THREADS * i] = g_norm2[tid + THREADS * i];

    // Build A: fp16 split of this thread's query row into h/m tiles.
    // 128B/row; 16B chunks XOR-swizzled by row&7 (conflict-free ldmatrix).
    {
        const float4* xr = reinterpret_cast<const float4*>(
            x + ((size_t)blockIdx.x * MROWS + tid) * DIM);
#pragma unroll
        for (int ch = 0; ch < 8; ch++) {
            float4 v0 = xr[2 * ch], v1 = xr[2 * ch + 1];
            float f[8] = {v0.x, v0.y, v0.z, v0.w, v1.x, v1.y, v1.z, v1.w};
            uint32_t hp[4], mp[4];
#pragma unroll
            for (int j = 0; j < 4; j++) {
                __half h0 = __float2half_rn(f[2 * j]);
                __half m0 = __float2half_rn(f[2 * j] - __half2float(h0));
                __half h1 = __float2half_rn(f[2 * j + 1]);
                __half m1 = __float2half_rn(f[2 * j + 1] - __half2float(h1));
                __half2 hh(h0, h1), mm(m0, m1);
                hp[j] = *reinterpret_cast<uint32_t*>(&hh);
                mp[j] = *reinterpret_cast<uint32_t*>(&mm);
            }
            uint32_t off = tid * 128 + ((ch ^ (tid & 7)) << 4);
            *reinterpret_cast<uint4*>(smem + SM_A + off) =
                make_uint4(hp[0], hp[1], hp[2], hp[3]);
            *reinterpret_cast<uint4*>(smem + SM_A + A_SUB + off) =
                make_uint4(mp[0], mp[1], mp[2], mp[3]);
        }
    }

    float best[4];
    int bidx[4];
#pragma unroll
    for (int s = 0; s < 4; s++) { best[s] = __int_as_float(0x7f800000); bidx[s] = 0; }

    for (int nt = 0; nt < NTILES; nt++) {
        const int cur = nt & 1;
        if (nt + 1 < NTILES) {
            stageB(nt + 1, cur ^ 1);
            asm volatile("cp.async.commit_group;");
            asm volatile("cp.async.wait_group 1;");
        } else {
            asm volatile("cp.async.wait_group 0;");
        }
        __syncthreads();   // current buffer (and A/norms on nt=0) visible

        float cc[2][8][4];
#pragma unroll
        for (int mt = 0; mt < 2; mt++)
#pragma unroll
            for (int n8 = 0; n8 < 8; n8++)
#pragma unroll
                for (int j = 0; j < 4; j++) cc[mt][n8][j] = 0.f;

#pragma unroll
        for (int ks = 0; ks < 4; ks++) {
            // A fragments: both splits x both m-tiles at this ks.
            uint32_t a[2][2][4];
#pragma unroll
            for (int sp = 0; sp < 2; sp++)
#pragma unroll
                for (int mt = 0; mt < 2; mt++) {
                    int r = wid * 32 + mt * 16 + (lane & 15);
                    uint32_t ad = sb + SM_A + sp * A_SUB + r * 128 +
                        (((2 * ks + (lane >> 4)) ^ (lane & 7)) << 4);
                    LDSM_X4(a[sp][mt][0], a[sp][mt][1], a[sp][mt][2],
                            a[sp][mt][3], ad);
                }
#pragma unroll
            for (int np = 0; np < 4; np++) {
                // B fragments for both splits: x4 load = two n8 blocks each.
                int n = 16 * np + ((lane >> 4) << 3) + (lane & 7);
                int ch = 2 * ks + ((lane >> 3) & 1);
                uint32_t boff = n * 128 + ((ch ^ (lane & 7)) << 4);
                uint32_t b[2][4];
#pragma unroll
                for (int sp = 0; sp < 2; sp++)
                    LDSM_X4(b[sp][0], b[sp][1], b[sp][2], b[sp][3],
                            sb + SM_B + cur * BUFB + sp * B_SUB + boff);
                // 4 terms = full (h+m) x (h+m) product.
#pragma unroll
                for (int sa = 0; sa < 2; sa++)
#pragma unroll
                    for (int sp = 0; sp < 2; sp++)
#pragma unroll
                        for (int mt = 0; mt < 2; mt++) {
                            MMA_F16(cc[mt][2 * np][0], cc[mt][2 * np][1],
                                    cc[mt][2 * np][2], cc[mt][2 * np][3],
                                    a[sa][mt][0], a[sa][mt][1],
                                    a[sa][mt][2], a[sa][mt][3],
                                    b[sp][0], b[sp][1]);
                            MMA_F16(cc[mt][2 * np + 1][0], cc[mt][2 * np + 1][1],
                                    cc[mt][2 * np + 1][2], cc[mt][2 * np + 1][3],
                                    a[sa][mt][0], a[sa][mt][1],
                                    a[sa][mt][2], a[sa][mt][3],
                                    b[sp][2], b[sp][3]);
                        }
            }
        }

        // Fused epilogue: score = norm2 - 2*dot, running argmin per row-slot.
#pragma unroll
        for (int n8 = 0; n8 < 8; n8++) {
            int col = nt * NT_CODES + n8 * 8 + (lane & 3) * 2;
            float sn0 = snorm[col], sn1 = snorm[col + 1];
#pragma unroll
            for (int mt = 0; mt < 2; mt++) {
                float s00 = fmaf(-2.f, cc[mt][n8][0], sn0);
                float s01 = fmaf(-2.f, cc[mt][n8][1], sn1);
                float s10 = fmaf(-2.f, cc[mt][n8][2], sn0);
                float s11 = fmaf(-2.f, cc[mt][n8][3], sn1);
                int s = mt * 2;
                if (s00 < best[s]) { best[s] = s00; bidx[s] = col; }
                if (s01 < best[s]) { best[s] = s01; bidx[s] = col + 1; }
                if (s10 < best[s + 1]) { best[s + 1] = s10; bidx[s + 1] = col; }
                if (s11 < best[s + 1]) { best[s + 1] = s11; bidx[s + 1] = col + 1; }
            }
        }
        __syncthreads();   // all reads of buffer `cur` done before overwrite
    }

    // Cross-lane reduce within each quad (lanes sharing a row), idx tiebreak.
#pragma unroll
    for (int s = 0; s < 4; s++) {
#pragma unroll
        for (int off = 1; off <= 2; off <<= 1) {
            float ob = __shfl_xor_sync(0xffffffffu, best[s], off);
            int oi = __shfl_xor_sync(0xffffffffu, bidx[s], off);
            if (ob < best[s] || (ob == best[s] && oi < bidx[s])) {
                best[s] = ob;
                bidx[s] = oi;
            }
        }
    }

    __syncthreads();
    int* sidx = reinterpret_cast<int*>(smem + SM_B);   // B buffers now free
    if ((lane & 3) == 0) {
#pragma unroll
        for (int s = 0; s < 4; s++) {
            int row = wid * 32 + (s >> 1) * 16 + (lane >> 2) + (s & 1) * 8;
            sidx[row] = bidx[s];
        }
    }
    __syncthreads();

    // Gather winning fp32 codebook row; thread tid handles query row tid.
    {
        int k = sidx[tid];
        const float4* e = reinterpret_cast<const float4*>(g_embT + (size_t)k * DIM);
        float4* o = reinterpret_cast<float4*>(
            out + ((size_t)blockIdx.x * MROWS + tid) * DIM);
#pragma unroll
        for (int i = 0; i < DIM / 4; i++) o[i] = e[i];
    }
}

extern "C" void kernel_launch(void* const* d_in, const int* in_sizes, int n_in,
                              void* d_out, int out_size) {
    const float* x   = (const float*)d_in[0];   // [128,1024,64] f32
    const float* emb = (const float*)d_in[1];   // [64,1024] f32
    float* out = (float*)d_out;

    cudaFuncSetAttribute(vq_main_kernel,
                         cudaFuncAttributeMaxDynamicSharedMemorySize, DYN_SMEM);

    vq_split_kernel<<<(NUM_K * DIM) / 256, 256>>>(emb);
    vq_norm_kernel<<<NUM_K / 256, 256>>>();
    vq_main_kernel<<<GRID, THREADS, DYN_SMEM>>>(x, out);
}

// round 13
// speedup vs baseline: 4.5389x; 1.8321x over previous
#include <cuda_runtime.h>
#include <cuda_fp16.h>
#include <cstdint>

// VectorQuantizer: x:[128,1024,64] f32, embeddings:[64,1024] f32.
// score(f,k) = ||e_k||^2 - 2 f.e_k (||f||^2 per-row const); out = e_{argmin}.
//
// Tensor path: legacy mma.sync.m16n8k16 (tcgen05 gated off by the harness's
// compute_103 PTX target).
//
// R11: fp16 2-way split, THREE terms:
//   v = h + m + l,  h=fp16(v), m=fp16(v-h)
//   dot ~= hh + hm + mh      (mm dropped: rms ~4e-8, below the hl/lh
//   residual ~2e-7 and far below the reference's own fp32 noise ~5e-6)
// -25% MMA work vs the 4-term R10 kernel; zero argmin-flip risk class.

#define NUM_K  1024
#define DIM    64
#define N_ROWS (128 * 1024)
#define MROWS  128
#define NT_CODES 64
#define NTILES (NUM_K / NT_CODES)  // 16
#define THREADS 128
#define GRID   (N_ROWS / MROWS)    // 1024

__device__ __half g_eh[NUM_K * DIM];
__device__ __half g_em[NUM_K * DIM];
__device__ float g_norm2[NUM_K];
__device__ float g_embT[NUM_K * DIM];    // fp32 codebook [k][d] for gather

// smem layout (bytes)
#define SM_A     0                  // 2 splits x 128 rows x 128B = 32768
#define A_SUB    16384
#define SM_B     32768              // 2 buffers x 2 splits x 64 rows x 128B
#define BUFB     16384
#define B_SUB    8192
#define SM_NORM  65536              // 1024 f32
#define DYN_SMEM 69632

static __device__ __forceinline__ uint32_t smem_u32(const void* p) {
    uint32_t a;
    asm("{ .reg .u64 t; cvta.to.shared.u64 t, %1; cvt.u32.u64 %0, t; }"
        : "=r"(a) : "l"(p));
    return a;
}
static __device__ __forceinline__ void cp_async16(uint32_t dst, const void* src) {
    asm volatile("cp.async.cg.shared.global [%0], [%1], 16;"
                 :: "r"(dst), "l"(src));
}

#define LDSM_X4(r0, r1, r2, r3, a) \
    asm volatile("ldmatrix.sync.aligned.m8n8.x4.shared.b16 {%0,%1,%2,%3}, [%4];" \
                 : "=r"(r0), "=r"(r1), "=r"(r2), "=r"(r3) : "r"(a))
#define MMA_F16(c0, c1, c2, c3, a0, a1, a2, a3, b0, b1) \
    asm volatile("mma.sync.aligned.m16n8k16.row.col.f32.f16.f16.f32 " \
                 "{%0,%1,%2,%3}, {%4,%5,%6,%7}, {%8,%9}, {%0,%1,%2,%3};" \
                 : "+f"(c0), "+f"(c1), "+f"(c2), "+f"(c3) \
                 : "r"(a0), "r"(a1), "r"(a2), "r"(a3), "r"(b0), "r"(b1))

// ---------------------------------------------------------------------------
// Prep 1: elementwise transpose + fp16 split. i = d*1024 + k (coalesced read).
// ---------------------------------------------------------------------------
__global__ void vq_split_kernel(const float* __restrict__ emb) {
    int i = blockIdx.x * blockDim.x + threadIdx.x;   // 65536 elements
    int d = i >> 10, k = i & 1023;
    float v = emb[i];
    __half h = __float2half_rn(v);
    __half m = __float2half_rn(v - __half2float(h));
    g_embT[k * DIM + d] = v;
    g_eh[k * DIM + d] = h;
    g_em[k * DIM + d] = m;
}
// Prep 2: per-code squared norms (reads transposed rows contiguously).
__global__ void vq_norm_kernel() {
    int k = blockIdx.x * blockDim.x + threadIdx.x;
    const float4* r = reinterpret_cast<const float4*>(g_embT + (size_t)k * DIM);
    float acc = 0.f;
#pragma unroll
    for (int i = 0; i < DIM / 4; i++) {
        float4 v = r[i];
        acc = fmaf(v.x, v.x, acc);
        acc = fmaf(v.y, v.y, acc);
        acc = fmaf(v.z, v.z, acc);
        acc = fmaf(v.w, v.w, acc);
    }
    g_norm2[k] = acc;
}

// ---------------------------------------------------------------------------
__global__ void __launch_bounds__(THREADS, 3)
vq_main_kernel(const float* __restrict__ x, float* __restrict__ out) {
    extern __shared__ char smem[];
    const uint32_t sb = smem_u32(smem);
    const int tid = threadIdx.x;
    const int lane = tid & 31;
    const int wid = tid >> 5;

    // Stage B tile nt into buffer buf via cp.async (16B granules, swizzled).
    auto stageB = [&](int nt, int buf) {
        const int base = nt * NT_CODES * DIM;
#pragma unroll
        for (int s = 0; s < 2; s++) {
            const __half* g = (s == 0) ? g_eh : g_em;
#pragma unroll
            for (int i = 0; i < 4; i++) {
                int q = tid + THREADS * i;          // 16B chunk 0..511
                int row = q >> 3, ch = q & 7;
                uint32_t dst = sb + SM_B + buf * BUFB + s * B_SUB +
                               row * 128 + ((ch ^ (row & 7)) << 4);
                cp_async16(dst, reinterpret_cast<const char*>(g + base) + q * 16);
            }
        }
    };

    stageB(0, 0);
    asm volatile("cp.async.commit_group;");

    float* snorm = reinterpret_cast<float*>(smem + SM_NORM);
#pragma unroll
    for (int i = 0; i < NUM_K / THREADS; i++)
        snorm[tid + THREADS * i] = g_norm2[tid + THREADS * i];

    // Build A: fp16 split of this thread's query row into h/m tiles.
    // 128B/row; 16B chunks XOR-swizzled by row&7 (conflict-free ldmatrix).
    {
        const float4* xr = reinterpret_cast<const float4*>(
            x + ((size_t)blockIdx.x * MROWS + tid) * DIM);
#pragma unroll
        for (int ch = 0; ch < 8; ch++) {
            float4 v0 = xr[2 * ch], v1 = xr[2 * ch + 1];
            float f[8] = {v0.x, v0.y, v0.z, v0.w, v1.x, v1.y, v1.z, v1.w};
            uint32_t hp[4], mp[4];
#pragma unroll
            for (int j = 0; j < 4; j++) {
                __half h0 = __float2half_rn(f[2 * j]);
                __half m0 = __float2half_rn(f[2 * j] - __half2float(h0));
                __half h1 = __float2half_rn(f[2 * j + 1]);
                __half m1 = __float2half_rn(f[2 * j + 1] - __half2float(h1));
                __half2 hh(h0, h1), mm(m0, m1);
                hp[j] = *reinterpret_cast<uint32_t*>(&hh);
                mp[j] = *reinterpret_cast<uint32_t*>(&mm);
            }
            uint32_t off = tid * 128 + ((ch ^ (tid & 7)) << 4);
            *reinterpret_cast<uint4*>(smem + SM_A + off) =
                make_uint4(hp[0], hp[1], hp[2], hp[3]);
            *reinterpret_cast<uint4*>(smem + SM_A + A_SUB + off) =
                make_uint4(mp[0], mp[1], mp[2], mp[3]);
        }
    }

    float best[4];
    int bidx[4];
#pragma unroll
    for (int s = 0; s < 4; s++) { best[s] = __int_as_float(0x7f800000); bidx[s] = 0; }

    for (int nt = 0; nt < NTILES; nt++) {
        const int cur = nt & 1;
        if (nt + 1 < NTILES) {
            stageB(nt + 1, cur ^ 1);
            asm volatile("cp.async.commit_group;");
            asm volatile("cp.async.wait_group 1;");
        } else {
            asm volatile("cp.async.wait_group 0;");
        }
        __syncthreads();   // current buffer (and A/norms on nt=0) visible

        float cc[2][8][4];
#pragma unroll
        for (int mt = 0; mt < 2; mt++)
#pragma unroll
            for (int n8 = 0; n8 < 8; n8++)
#pragma unroll
                for (int j = 0; j < 4; j++) cc[mt][n8][j] = 0.f;

#pragma unroll
        for (int ks = 0; ks < 4; ks++) {
            // A fragments: both splits x both m-tiles at this ks.
            uint32_t a[2][2][4];
#pragma unroll
            for (int sp = 0; sp < 2; sp++)
#pragma unroll
                for (int mt = 0; mt < 2; mt++) {
                    int r = wid * 32 + mt * 16 + (lane & 15);
                    uint32_t ad = sb + SM_A + sp * A_SUB + r * 128 +
                        (((2 * ks + (lane >> 4)) ^ (lane & 7)) << 4);
                    LDSM_X4(a[sp][mt][0], a[sp][mt][1], a[sp][mt][2],
                            a[sp][mt][3], ad);
                }
#pragma unroll
            for (int np = 0; np < 4; np++) {
                // B fragments for both splits: x4 load = two n8 blocks each.
                int n = 16 * np + ((lane >> 4) << 3) + (lane & 7);
                int ch = 2 * ks + ((lane >> 3) & 1);
                uint32_t boff = n * 128 + ((ch ^ (lane & 7)) << 4);
                uint32_t b[2][4];
#pragma unroll
                for (int sp = 0; sp < 2; sp++)
                    LDSM_X4(b[sp][0], b[sp][1], b[sp][2], b[sp][3],
                            sb + SM_B + cur * BUFB + sp * B_SUB + boff);
                // 3 terms: (h,h), (h,m), (m,h)  [mm dropped, rms ~4e-8]
                const int TA[3] = {0, 0, 1};
                const int TB[3] = {0, 1, 0};
#pragma unroll
                for (int tm = 0; tm < 3; tm++)
#pragma unroll
                    for (int mt = 0; mt < 2; mt++) {
                        MMA_F16(cc[mt][2 * np][0], cc[mt][2 * np][1],
                                cc[mt][2 * np][2], cc[mt][2 * np][3],
                                a[TA[tm]][mt][0], a[TA[tm]][mt][1],
                                a[TA[tm]][mt][2], a[TA[tm]][mt][3],
                                b[TB[tm]][0], b[TB[tm]][1]);
                        MMA_F16(cc[mt][2 * np + 1][0], cc[mt][2 * np + 1][1],
                                cc[mt][2 * np + 1][2], cc[mt][2 * np + 1][3],
                                a[TA[tm]][mt][0], a[TA[tm]][mt][1],
                                a[TA[tm]][mt][2], a[TA[tm]][mt][3],
                                b[TB[tm]][2], b[TB[tm]][3]);
                    }
            }
        }

        // Fused epilogue: score = norm2 - 2*dot, running argmin per row-slot.
#pragma unroll
        for (int n8 = 0; n8 < 8; n8++) {
            int col = nt * NT_CODES + n8 * 8 + (lane & 3) * 2;
            float sn0 = snorm[col], sn1 = snorm[col + 1];
#pragma unroll
            for (int mt = 0; mt < 2; mt++) {
                float s00 = fmaf(-2.f, cc[mt][n8][0], sn0);
                float s01 = fmaf(-2.f, cc[mt][n8][1], sn1);
                float s10 = fmaf(-2.f, cc[mt][n8][2], sn0);
                float s11 = fmaf(-2.f, cc[mt][n8][3], sn1);
                int s = mt * 2;
                if (s00 < best[s]) { best[s] = s00; bidx[s] = col; }
                if (s01 < best[s]) { best[s] = s01; bidx[s] = col + 1; }
                if (s10 < best[s + 1]) { best[s + 1] = s10; bidx[s + 1] = col; }
                if (s11 < best[s + 1]) { best[s + 1] = s11; bidx[s + 1] = col + 1; }
            }
        }
        __syncthreads();   // all reads of buffer `cur` done before overwrite
    }

    // Cross-lane reduce within each quad (lanes sharing a row), idx tiebreak.
#pragma unroll
    for (int s = 0; s < 4; s++) {
#pragma unroll
        for (int off = 1; off <= 2; off <<= 1) {
            float ob = __shfl_xor_sync(0xffffffffu, best[s], off);
            int oi = __shfl_xor_sync(0xffffffffu, bidx[s], off);
            if (ob < best[s] || (ob == best[s] && oi < bidx[s])) {
                best[s] = ob;
                bidx[s] = oi;
            }
        }
    }

    __syncthreads();
    int* sidx = reinterpret_cast<int*>(smem + SM_B);   // B buffers now free
    if ((lane & 3) == 0) {
#pragma unroll
        for (int s = 0; s < 4; s++) {
            int row = wid * 32 + (s >> 1) * 16 + (lane >> 2) + (s & 1) * 8;
            sidx[row] = bidx[s];
        }
    }
    __syncthreads();

    // Gather winning fp32 codebook row; thread tid handles query row tid.
    {
        int k = sidx[tid];
        const float4* e = reinterpret_cast<const float4*>(g_embT + (size_t)k * DIM);
        float4* o = reinterpret_cast<float4*>(
            out + ((size_t)blockIdx.x * MROWS + tid) * DIM);
#pragma unroll
        for (int i = 0; i < DIM / 4; i++) o[i] = e[i];
    }
}

extern "C" void kernel_launch(void* const* d_in, const int* in_sizes, int n_in,
                              void* d_out, int out_size) {
    const float* x   = (const float*)d_in[0];   // [128,1024,64] f32
    const float* emb = (const float*)d_in[1];   // [64,1024] f32
    float* out = (float*)d_out;

    cudaFuncSetAttribute(vq_main_kernel,
                         cudaFuncAttributeMaxDynamicSharedMemorySize, DYN_SMEM);

    vq_split_kernel<<<(NUM_K * DIM) / 256, 256>>>(emb);
    vq_norm_kernel<<<NUM_K / 256, 256>>>();
    vq_main_kernel<<<GRID, THREADS, DYN_SMEM>>>(x, out);
}